// round 1
// baseline (speedup 1.0000x reference)
#include <cuda_runtime.h>

#define BB 256
#define TT 256
#define DD 80
#define HH 512
#define GG 2048   // 4*HH
#define KE 512
#define NBLK 128

// ---------------- device scratch (static allocation only) ----------------
__device__ float g_hA[BB*HH];
__device__ float g_hB[BB*HH];
__device__ float g_c [BB*HH];
__device__ float g_WencT[HH*GG];     // enc_W_hh transposed  [k][n]
__device__ float g_WxT  [DD*GG];     // enc_W_ih transposed  [d][n]
__device__ float g_Wdec0T[HH*GG];    // dec_W_hh transposed  [k][n]
__device__ float g_Wcomb [HH*GG];    // dec_W_hh^T + fc_W^T * dec_W_ih^T
__device__ float g_bias_enc[GG];
__device__ float g_bias_dec[GG];
__device__ float g_bcomb[GG];
__device__ float g_quant[BB*HH];
__device__ float g_lossp[BB];
__device__ int   g_idx[BB];
__device__ float g_Hbuf[(size_t)TT*BB*HH];   // decoder hidden history (134 MB)
__device__ unsigned g_bar;

// ---------------- helpers ----------------
__device__ __forceinline__ unsigned long long dupf(float v){
    unsigned long long r; asm("mov.b64 %0, {%1,%1};" : "=l"(r) : "f"(v)); return r;
}
__device__ __forceinline__ float2 ull2f(unsigned long long v){
    float2 r; asm("mov.b64 {%0,%1}, %2;" : "=f"(r.x), "=f"(r.y) : "l"(v)); return r;
}
__device__ __forceinline__ void ffma2(unsigned long long& d, unsigned long long a, unsigned long long b){
    asm("fma.rn.f32x2 %0, %1, %2, %0;" : "+l"(d) : "l"(a), "l"(b));
}
__device__ __forceinline__ float sigf(float x){ return 1.f/(1.f + __expf(-x)); }
__device__ __forceinline__ float tanh_f(float x){ return 2.f/(1.f + __expf(-2.f*x)) - 1.f; }

__device__ __forceinline__ void grid_sync(unsigned epoch){
    __syncthreads();
    if (threadIdx.x == 0){
        __threadfence();
        atomicAdd(&g_bar, 1u);
        unsigned target = (epoch + 1u) * NBLK;
        unsigned v;
        do {
            asm volatile("ld.acquire.gpu.u32 %0, [%1];" : "=r"(v) : "l"(&g_bar) : "memory");
        } while (v < target);
    }
    __syncthreads();
}

// stage 32 k-rows x 64 b-rows: element (r,kk) at src[r*stride + kk]
__device__ __forceinline__ void stage_h32(float hs[32][68], const float* __restrict__ src, int stride){
    int kk = threadIdx.x & 31, rb = threadIdx.x >> 5;
    #pragma unroll
    for (int i = 0; i < 8; i++)
        hs[kk][rb + i*8] = src[(size_t)(rb + i*8)*stride + kk];
}
__device__ __forceinline__ void stage_h16(float hs[32][68], const float* __restrict__ src, int stride){
    int kk = threadIdx.x & 15, rb = threadIdx.x >> 4;
    #pragma unroll
    for (int i = 0; i < 4; i++)
        hs[kk][rb + i*16] = src[(size_t)(rb + i*16)*stride + kk];
}
// stage W tile: wbase = W + kb*GG + j0 ; ws[kk][q][t16] = dup(W[kb+kk][q*512 + j0 + t16])
__device__ __forceinline__ void stage_w32(unsigned long long ws[32][4][16], const float* __restrict__ wbase){
    int c64 = threadIdx.x & 63, kk0 = threadIdx.x >> 6;
    int q = c64 >> 4, t16 = c64 & 15;
    #pragma unroll
    for (int i = 0; i < 8; i++){
        int kk = kk0 + i*4;
        ws[kk][q][t16] = dupf(wbase[(size_t)kk*GG + q*512 + t16]);
    }
}
__device__ __forceinline__ void stage_w16(unsigned long long ws[32][4][16], const float* __restrict__ wbase){
    int c64 = threadIdx.x & 63, kk0 = threadIdx.x >> 6;
    int q = c64 >> 4, t16 = c64 & 15;
    #pragma unroll
    for (int i = 0; i < 4; i++){
        int kk = kk0 + i*4;
        ws[kk][q][t16] = dupf(wbase[(size_t)kk*GG + q*512 + t16]);
    }
}

template<int KC>
__device__ __forceinline__ void mma_chunk(unsigned long long acc[4][2],
                                          const float hs[32][68],
                                          const unsigned long long ws[32][4][16],
                                          int tx, int ty){
    #pragma unroll
    for (int kk = 0; kk < KC; kk++){
        ulonglong2 hp = *(const ulonglong2*)&hs[kk][ty*4];
        #pragma unroll
        for (int q = 0; q < 4; q++){
            unsigned long long w = ws[kk][q][tx];
            ffma2(acc[q][0], hp.x, w);
            ffma2(acc[q][1], hp.y, w);
        }
    }
}

// ---------------- weight prep ----------------
__global__ void k_prep1(const float* __restrict__ eWih, const float* __restrict__ eWhh,
                        const float* __restrict__ ebi,  const float* __restrict__ ebh,
                        const float* __restrict__ dWhh, const float* __restrict__ dbi,
                        const float* __restrict__ dbh){
    const size_t NW = (size_t)HH*GG;          // 1048576
    const size_t NX = (size_t)DD*GG;          // 163840
    const size_t TOT = NW + NW + NX + GG + GG;
    for (size_t i = (size_t)blockIdx.x*blockDim.x + threadIdx.x; i < TOT; i += (size_t)gridDim.x*blockDim.x){
        if (i < NW){
            size_t k = i >> 11, n = i & 2047;
            g_WencT[i] = eWhh[n*HH + k];
        } else if (i < 2*NW){
            size_t ii = i - NW, k = ii >> 11, n = ii & 2047;
            g_Wdec0T[ii] = dWhh[n*HH + k];
        } else if (i < 2*NW + NX){
            size_t ii = i - 2*NW, d = ii >> 11, n = ii & 2047;
            g_WxT[ii] = eWih[n*DD + d];
        } else if (i < 2*NW + NX + GG){
            size_t n = i - (2*NW + NX);
            g_bias_enc[n] = ebi[n] + ebh[n];
        } else {
            size_t n = i - (2*NW + NX + GG);
            g_bias_dec[n] = dbi[n] + dbh[n];
        }
    }
}

// Wcomb[k][n] = dec_W_hh[n][k] + sum_d fc_W[d][k] * dec_W_ih[n][d]
__global__ void k_wcomb(const float* __restrict__ dWih, const float* __restrict__ dWhh,
                        const float* __restrict__ fcW){
    __shared__ float sfc[DD*32];   // [d][kk]
    __shared__ float sW [64*DD];   // [nn][d]
    int kt = blockIdx.x & 15;      // 16 k-tiles of 32
    int nt = blockIdx.x >> 4;      // 32 n-tiles of 64
    int k0 = kt*32, n0 = nt*64;
    int tid = threadIdx.x;
    {   int kk = tid & 31, db = tid >> 5;
        #pragma unroll
        for (int i = 0; i < 10; i++){
            int d = db + i*8;
            sfc[d*32 + kk] = fcW[(size_t)d*HH + k0 + kk];
        }
    }
    for (int l = tid; l < 64*DD; l += 256)
        sW[l] = dWih[(size_t)n0*DD + l];
    __syncthreads();
    int kk = tid & 31;
    int nnb = (tid >> 5) * 8;
    float acc[8];
    #pragma unroll
    for (int i = 0; i < 8; i++)
        acc[i] = dWhh[(size_t)(n0 + nnb + i)*HH + k0 + kk];
    for (int d = 0; d < DD; d++){
        float f = sfc[d*32 + kk];
        #pragma unroll
        for (int i = 0; i < 8; i++)
            acc[i] += f * sW[(nnb + i)*DD + d];
    }
    #pragma unroll
    for (int i = 0; i < 8; i++)
        g_Wcomb[(size_t)(k0 + kk)*GG + n0 + nnb + i] = acc[i];
}

__global__ void k_bcomb(const float* __restrict__ dWih, const float* __restrict__ fcb){
    int n = blockIdx.x*blockDim.x + threadIdx.x;
    if (n < GG){
        float b = g_bias_dec[n];
        for (int d = 0; d < DD; d++)
            b += fcb[d] * dWih[(size_t)n*DD + d];
        g_bcomb[n] = b;
    }
}

__global__ void k_init(){
    int i = blockIdx.x*blockDim.x + threadIdx.x;
    if (i < BB*HH){ g_hA[i] = 0.f; g_c[i] = 0.f; }
    if (i == 0) g_bar = 0u;
}

__global__ void k_decinit(){
    int i = blockIdx.x*blockDim.x + threadIdx.x;
    if (i < BB*HH){ g_hA[i] = g_quant[i]; g_c[i] = 0.f; }
    if (i == 0) g_bar = 0u;
}

// ---------------- persistent encoder ----------------
__global__ void __launch_bounds__(256, 1) k_encoder(const float* __restrict__ traj){
    __shared__ __align__(16) float hs[32][68];
    __shared__ unsigned long long ws[32][4][16];
    const int tid = threadIdx.x;
    const int rg = blockIdx.x >> 5, cg = blockIdx.x & 31;
    const int row0 = rg*64, j0 = cg*16;
    const int tx = tid & 15, ty = tid >> 4;
    const int j = j0 + tx;
    const int r0 = row0 + ty*4;

    float bias[4];
    #pragma unroll
    for (int q = 0; q < 4; q++) bias[q] = g_bias_enc[q*512 + j];

    for (int t = 0; t < TT; t++){
        const float* hr = (t & 1) ? g_hB : g_hA;
        float*       hw = (t & 1) ? g_hA : g_hB;

        unsigned long long acc[4][2];
        #pragma unroll
        for (int q = 0; q < 4; q++){
            unsigned long long b = dupf(bias[q]);
            acc[q][0] = b; acc[q][1] = b;
        }

        // h part: K = 512, 16 chunks of 32
        for (int c = 0; c < 16; c++){
            __syncthreads();
            stage_h32(hs, hr + (size_t)row0*HH + c*32, HH);
            stage_w32(ws, g_WencT + (size_t)(c*32)*GG + j0);
            __syncthreads();
            mma_chunk<32>(acc, hs, ws, tx, ty);
        }
        // x part: K = 80 (32 + 32 + 16)
        const float* xbase = traj + ((size_t)row0*TT + t)*DD;
        for (int xc = 0; xc < 2; xc++){
            __syncthreads();
            stage_h32(hs, xbase + xc*32, TT*DD);
            stage_w32(ws, g_WxT + (size_t)(xc*32)*GG + j0);
            __syncthreads();
            mma_chunk<32>(acc, hs, ws, tx, ty);
        }
        __syncthreads();
        stage_h16(hs, xbase + 64, TT*DD);
        stage_w16(ws, g_WxT + (size_t)64*GG + j0);
        __syncthreads();
        mma_chunk<16>(acc, hs, ws, tx, ty);

        // elementwise LSTM update
        #pragma unroll
        for (int p = 0; p < 2; p++){
            float2 vi = ull2f(acc[0][p]);
            float2 vf = ull2f(acc[1][p]);
            float2 vg = ull2f(acc[2][p]);
            float2 vo = ull2f(acc[3][p]);
            int r = r0 + p*2;
            {
                size_t a = (size_t)r*HH + j;
                float cn = sigf(vf.x)*g_c[a] + sigf(vi.x)*tanh_f(vg.x);
                g_c[a] = cn;
                hw[a] = sigf(vo.x)*tanh_f(cn);
            }
            {
                size_t a = (size_t)(r+1)*HH + j;
                float cn = sigf(vf.y)*g_c[a] + sigf(vi.y)*tanh_f(vg.y);
                g_c[a] = cn;
                hw[a] = sigf(vo.y)*tanh_f(cn);
            }
        }
        grid_sync((unsigned)t);
    }
    // T=256 even -> final hidden state ends up in g_hA
}

// ---------------- VQ ----------------
__global__ void k_vq(const float* __restrict__ emb){
    int b = blockIdx.x, tid = threadIdx.x;
    __shared__ float zs[HH];
    __shared__ float rs[256];
    __shared__ int   rk[256];
    zs[tid]       = g_hA[(size_t)b*HH + tid];
    zs[tid + 256] = g_hA[(size_t)b*HH + tid + 256];
    __syncthreads();
    float bestS = 3.4e38f; int bestK = 0;
    #pragma unroll
    for (int kq = 0; kq < 2; kq++){
        int k = tid + kq*256;
        const float* e = emb + (size_t)k*HH;
        float s = 0.f, dt = 0.f;
        for (int jj = 0; jj < HH; jj++){ float ev = e[jj]; s += ev*ev; dt += ev*zs[jj]; }
        float score = s - 2.f*dt;
        if (score < bestS || (score == bestS && k < bestK)){ bestS = score; bestK = k; }
    }
    rs[tid] = bestS; rk[tid] = bestK;
    __syncthreads();
    for (int s = 128; s > 0; s >>= 1){
        if (tid < s){
            if (rs[tid+s] < rs[tid] || (rs[tid+s] == rs[tid] && rk[tid+s] < rk[tid])){
                rs[tid] = rs[tid+s]; rk[tid] = rk[tid+s];
            }
        }
        __syncthreads();
    }
    int idx = rk[0];
    if (tid == 0) g_idx[b] = idx;
    float lp = 0.f;
    #pragma unroll
    for (int kq = 0; kq < 2; kq++){
        int jj = tid + kq*256;
        float q = emb[(size_t)idx*HH + jj];
        g_quant[(size_t)b*HH + jj] = q;
        float dz = q - zs[jj];
        lp += dz*dz;
    }
    __syncthreads();
    rs[tid] = lp;
    __syncthreads();
    for (int s = 128; s > 0; s >>= 1){
        if (tid < s) rs[tid] += rs[tid+s];
        __syncthreads();
    }
    if (tid == 0) g_lossp[b] = rs[0];
}

__global__ void k_vqfinish(float* __restrict__ out){
    const size_t OFF = (size_t)BB*TT*DD;
    int tid = threadIdx.x;
    if (tid == 0){
        float tot = 0.f;
        for (int i = 0; i < BB; i++) tot += g_lossp[i];
        out[OFF] = 1.25f * tot / (float)(BB*HH);
    }
    out[OFF + 1 + tid] = (float)g_idx[tid];
}

// ---------------- persistent decoder ----------------
__global__ void __launch_bounds__(256, 1) k_decoder(){
    __shared__ __align__(16) float hs[32][68];
    __shared__ unsigned long long ws[32][4][16];
    const int tid = threadIdx.x;
    const int rg = blockIdx.x >> 5, cg = blockIdx.x & 31;
    const int row0 = rg*64, j0 = cg*16;
    const int tx = tid & 15, ty = tid >> 4;
    const int j = j0 + tx;
    const int r0 = row0 + ty*4;

    for (int t = 0; t < TT; t++){
        const float* hr = (t & 1) ? g_hB : g_hA;
        float*       hw = (t & 1) ? g_hA : g_hB;
        const float* W  = (t == 0) ? g_Wdec0T : g_Wcomb;
        const float* bp = (t == 0) ? g_bias_dec : g_bcomb;

        unsigned long long acc[4][2];
        #pragma unroll
        for (int q = 0; q < 4; q++){
            unsigned long long b = dupf(bp[q*512 + j]);
            acc[q][0] = b; acc[q][1] = b;
        }
        for (int c = 0; c < 16; c++){
            __syncthreads();
            stage_h32(hs, hr + (size_t)row0*HH + c*32, HH);
            stage_w32(ws, W + (size_t)(c*32)*GG + j0);
            __syncthreads();
            mma_chunk<32>(acc, hs, ws, tx, ty);
        }
        #pragma unroll
        for (int p = 0; p < 2; p++){
            float2 vi = ull2f(acc[0][p]);
            float2 vf = ull2f(acc[1][p]);
            float2 vg = ull2f(acc[2][p]);
            float2 vo = ull2f(acc[3][p]);
            int r = r0 + p*2;
            {
                size_t a = (size_t)r*HH + j;
                float cn = sigf(vf.x)*g_c[a] + sigf(vi.x)*tanh_f(vg.x);
                g_c[a] = cn;
                float hv = sigf(vo.x)*tanh_f(cn);
                hw[a] = hv;
                g_Hbuf[((size_t)t*BB + r)*HH + j] = hv;
            }
            {
                size_t a = (size_t)(r+1)*HH + j;
                float cn = sigf(vf.y)*g_c[a] + sigf(vi.y)*tanh_f(vg.y);
                g_c[a] = cn;
                float hv = sigf(vo.y)*tanh_f(cn);
                hw[a] = hv;
                g_Hbuf[((size_t)t*BB + r + 1)*HH + j] = hv;
            }
        }
        grid_sync((unsigned)t);
    }
}

// ---------------- recon head: out[b][t][d] = Hbuf[t][b][:] . fc_W[d][:] + fc_b[d] ----------------
__global__ void __launch_bounds__(256) k_recon(const float* __restrict__ fcW,
                                               const float* __restrict__ fcb,
                                               float* __restrict__ out){
    __shared__ __align__(16) float hs[32][68];
    __shared__ unsigned long long wsd[32][DD];
    int t = blockIdx.x;
    int b0 = blockIdx.y * 64;
    int tid = threadIdx.x;
    int txd = tid & 15, tyb = tid >> 4;

    unsigned long long acc[5][2];
    #pragma unroll
    for (int s = 0; s < 5; s++){ acc[s][0] = 0ull; acc[s][1] = 0ull; }

    for (int c = 0; c < 16; c++){
        __syncthreads();
        stage_h32(hs, g_Hbuf + ((size_t)t*BB + b0)*HH + c*32, HH);
        {
            int kk = tid & 31, db = tid >> 5;
            #pragma unroll
            for (int i = 0; i < 10; i++){
                int d = db + i*8;
                wsd[kk][d] = dupf(fcW[(size_t)d*HH + c*32 + kk]);
            }
        }
        __syncthreads();
        #pragma unroll
        for (int kk = 0; kk < 32; kk++){
            ulonglong2 hp = *(const ulonglong2*)&hs[kk][tyb*4];
            #pragma unroll
            for (int s = 0; s < 5; s++){
                unsigned long long w = wsd[kk][txd + 16*s];
                ffma2(acc[s][0], hp.x, w);
                ffma2(acc[s][1], hp.y, w);
            }
        }
    }
    #pragma unroll
    for (int s = 0; s < 5; s++){
        int d = txd + 16*s;
        float bv = fcb[d];
        #pragma unroll
        for (int p = 0; p < 2; p++){
            float2 v = ull2f(acc[s][p]);
            int b = b0 + tyb*4 + p*2;
            out[((size_t)b*TT + t)*DD + d]     = v.x + bv;
            out[((size_t)(b+1)*TT + t)*DD + d] = v.y + bv;
        }
    }
}

// ---------------- launcher ----------------
extern "C" void kernel_launch(void* const* d_in, const int* in_sizes, int n_in,
                              void* d_out, int out_size){
    (void)in_sizes; (void)n_in; (void)out_size;
    const float* traj = (const float*)d_in[0];
    // d_in[1] = seq_len (constant 256, known at compile time)
    const float* eWih = (const float*)d_in[2];
    const float* eWhh = (const float*)d_in[3];
    const float* ebi  = (const float*)d_in[4];
    const float* ebh  = (const float*)d_in[5];
    const float* emb  = (const float*)d_in[6];
    const float* dWih = (const float*)d_in[7];
    const float* dWhh = (const float*)d_in[8];
    const float* dbi  = (const float*)d_in[9];
    const float* dbh  = (const float*)d_in[10];
    const float* fcW  = (const float*)d_in[11];
    const float* fcb  = (const float*)d_in[12];
    float* out = (float*)d_out;

    k_prep1<<<4096, 256>>>(eWih, eWhh, ebi, ebh, dWhh, dbi, dbh);
    k_wcomb<<<512, 256>>>(dWih, dWhh, fcW);
    k_bcomb<<<8, 256>>>(dWih, fcb);
    k_init<<<512, 256>>>();
    k_encoder<<<NBLK, 256>>>(traj);
    k_vq<<<BB, 256>>>(emb);
    k_vqfinish<<<1, 256>>>(out);
    k_decinit<<<512, 256>>>();
    k_decoder<<<NBLK, 256>>>();
    k_recon<<<dim3(TT, 4), 256>>>(fcW, fcb, out);
}

// round 2
// speedup vs baseline: 1.6187x; 1.6187x over previous
#include <cuda_runtime.h>

#define BB 256
#define TT 256
#define DD 80
#define HH 512
#define GG 2048   // 4*HH
#define NBLK 128
#define WSP_E 596     // enc W smem k-stride (odd multiple of 16B)
#define WSP_D 516     // dec W smem k-stride
#define HS_STRIDE 36  // h chunk smem stride (odd multiple of 16B)
#define HS_BUF (64*HS_STRIDE)
#define NCH_E 19
#define NCH_D 16

// ---------------- device scratch ----------------
__device__ float g_hA[BB*HH];
__device__ float g_hB[BB*HH];
__device__ float g_Wcomb[(size_t)GG*HH];   // dec: W_hh + W_ih * fc_W   [n][k]
__device__ float g_bias_enc[GG];
__device__ float g_bcomb[GG];
__device__ float g_quant[BB*HH];
__device__ float g_tmpT[DD*BB];            // (q@fcW^T + fcb) transposed [d][b]
__device__ float g_corr[(size_t)BB*GG];    // step-0 correction [b][n]
__device__ float g_lossp[BB];
__device__ int   g_idx[BB];
__device__ float g_Hbuf[(size_t)TT*BB*HH]; // decoder hidden history
__device__ unsigned g_bar;

// ---------------- helpers ----------------
__device__ __forceinline__ unsigned long long dupf(float v){
    unsigned long long r; asm("mov.b64 %0, {%1,%1};" : "=l"(r) : "f"(v)); return r;
}
__device__ __forceinline__ float2 ull2f(unsigned long long v){
    float2 r; asm("mov.b64 {%0,%1}, %2;" : "=f"(r.x), "=f"(r.y) : "l"(v)); return r;
}
__device__ __forceinline__ void ffma2(unsigned long long& d, unsigned long long a, unsigned long long b){
    asm("fma.rn.f32x2 %0, %1, %2, %0;" : "+l"(d) : "l"(a), "l"(b));
}
__device__ __forceinline__ float sigf(float x){ return 1.f/(1.f + __expf(-x)); }
__device__ __forceinline__ float tanh_f(float x){ return 2.f/(1.f + __expf(-2.f*x)) - 1.f; }

__device__ __forceinline__ void grid_sync(unsigned epoch){
    __syncthreads();
    if (threadIdx.x == 0){
        __threadfence();
        atomicAdd(&g_bar, 1u);
        unsigned target = (epoch + 1u) * NBLK;
        unsigned v;
        do {
            asm volatile("ld.acquire.gpu.u32 %0, [%1];" : "=r"(v) : "l"(&g_bar) : "memory");
        } while (v < target);
    }
    __syncthreads();
}

// K-paired MMA: acc holds {even-k partial, odd-k partial} per output.
// hb: thread's h base (local row ty*4, k 0), wb: ws + tx*WSP + koff.
template<int N4, int WSP>
__device__ __forceinline__ void mma_k(unsigned long long acc[4][4],
                                      const float* __restrict__ hb,
                                      const float* __restrict__ wb){
    #pragma unroll
    for (int k4 = 0; k4 < N4; k4++){
        ulonglong2 h[4];
        #pragma unroll
        for (int i = 0; i < 4; i++)
            h[i] = *reinterpret_cast<const ulonglong2*>(hb + i*HS_STRIDE + k4*4);
        #pragma unroll
        for (int q = 0; q < 4; q++){
            ulonglong2 w = *reinterpret_cast<const ulonglong2*>(wb + q*16*WSP + k4*4);
            #pragma unroll
            for (int i = 0; i < 4; i++){
                ffma2(acc[q][i], h[i].x, w.x);
                ffma2(acc[q][i], h[i].y, w.y);
            }
        }
    }
}

// ---------------- prep kernels ----------------
__global__ void k_bias(const float* __restrict__ ebi, const float* __restrict__ ebh,
                       const float* __restrict__ dbi, const float* __restrict__ dbh,
                       const float* __restrict__ dWih, const float* __restrict__ fcb){
    int n = blockIdx.x*blockDim.x + threadIdx.x;
    if (n < GG){
        g_bias_enc[n] = ebi[n] + ebh[n];
        float b = dbi[n] + dbh[n];
        const float* w = dWih + (size_t)n*DD;
        #pragma unroll 4
        for (int d = 0; d < DD; d++) b += fcb[d]*w[d];
        g_bcomb[n] = b;
    }
}

// Wcomb[n][k] = dWhh[n][k] + sum_d dWih[n][d] * fcW[d][k]
__global__ void k_wcomb(const float* __restrict__ dWih, const float* __restrict__ dWhh,
                        const float* __restrict__ fcW){
    __shared__ float sf[DD][64];
    __shared__ float sw[32][DD];
    int nt = blockIdx.x >> 3, kt = blockIdx.x & 7;
    int n0 = nt*32, k0 = kt*64;
    int tid = threadIdx.x;
    for (int idx = tid; idx < DD*64; idx += 256){
        int d = idx >> 6, kk = idx & 63;
        sf[d][kk] = fcW[(size_t)d*HH + k0 + kk];
    }
    for (int idx = tid; idx < 32*DD; idx += 256){
        int nn = idx / DD, d = idx % DD;
        sw[nn][d] = dWih[(size_t)(n0+nn)*DD + d];
    }
    __syncthreads();
    int nn = tid >> 3, kb = (tid & 7)*8;
    float a[8];
    #pragma unroll
    for (int i = 0; i < 8; i++) a[i] = dWhh[(size_t)(n0+nn)*HH + k0 + kb + i];
    for (int d = 0; d < DD; d++){
        float w = sw[nn][d];
        #pragma unroll
        for (int i = 0; i < 8; i++) a[i] += w * sf[d][kb+i];
    }
    #pragma unroll
    for (int i = 0; i < 8; i++) g_Wcomb[(size_t)(n0+nn)*HH + k0 + kb + i] = a[i];
}

// tmpT[d][b] = quant[b] . fcW[d] + fcb[d]
__global__ void k_x1(const float* __restrict__ fcW, const float* __restrict__ fcb){
    int b = blockIdx.x, tid = threadIdx.x;
    __shared__ float qs[HH];
    qs[tid]       = g_quant[(size_t)b*HH + tid];
    qs[tid + 256] = g_quant[(size_t)b*HH + tid + 256];
    __syncthreads();
    if (tid < DD){
        const float* w = fcW + (size_t)tid*HH;
        float s = fcb[tid];
        for (int k = 0; k < HH; k++) s += w[k]*qs[k];
        g_tmpT[tid*BB + b] = s;
    }
}

// corr[b][n] = sum_d tmpT[d][b] * dWih[n][d]
__global__ void k_corr(const float* __restrict__ dWih){
    int n = blockIdx.x, b = threadIdx.x;
    __shared__ float wd[DD];
    if (b < DD) wd[b] = dWih[(size_t)n*DD + b];
    __syncthreads();
    float s = 0.f;
    #pragma unroll 4
    for (int d = 0; d < DD; d++) s += wd[d] * g_tmpT[d*BB + b];
    g_corr[(size_t)b*GG + n] = s;
}

__global__ void k_init(){
    int i = blockIdx.x*blockDim.x + threadIdx.x;
    if (i < BB*HH) g_hA[i] = 0.f;
    if (i == 0) g_bar = 0u;
}
__global__ void k_decinit(){
    int i = blockIdx.x*blockDim.x + threadIdx.x;
    if (i < BB*HH) g_hA[i] = g_quant[i];
    if (i == 0) g_bar = 0u;
}

// ---------------- persistent encoder ----------------
// smem: ws[64][WSP_E] (k 0..79 = x weights, 80..591 = h weights) + hs[2][64][36]
__global__ void __launch_bounds__(256, 1) k_encoder(const float* __restrict__ traj,
                                                    const float* __restrict__ eWih,
                                                    const float* __restrict__ eWhh){
    extern __shared__ float sm[];
    float* ws = sm;
    float* hs = sm + 64*WSP_E;
    const int tid = threadIdx.x;
    const int rg = blockIdx.x >> 5, cg = blockIdx.x & 31;
    const int row0 = rg*64, j0 = cg*16;
    const int tx = tid & 15, ty = tid >> 4;
    const int j = j0 + tx;
    const int lr = tid >> 2, t4 = tid & 3;

    // resident W load (one-time)
    {
        int c = tid >> 2, l4 = tid & 3;
        int n = (c >> 4)*512 + j0 + (c & 15);
        for (int k0 = l4*4; k0 < DD; k0 += 16)
            *(float4*)&ws[c*WSP_E + k0] = *(const float4*)&eWih[(size_t)n*DD + k0];
        for (int k0 = l4*4; k0 < HH; k0 += 16)
            *(float4*)&ws[c*WSP_E + DD + k0] = *(const float4*)&eWhh[(size_t)n*HH + k0];
    }
    float bias[4];
    #pragma unroll
    for (int q = 0; q < 4; q++) bias[q] = g_bias_enc[q*HH + j];
    float cst[4] = {0.f, 0.f, 0.f, 0.f};

    int pb = 0;
    // stage chunk 0 of t=0 (x chunk 0) into buf0
    {
        const float* src = traj + ((size_t)(row0+lr)*TT + 0)*DD + t4*8;
        float4 p0 = ((const float4*)src)[0];
        float4 p1 = ((const float4*)src)[1];
        float* dst = &hs[0*HS_BUF + lr*HS_STRIDE + t4*8];
        ((float4*)dst)[0] = p0; ((float4*)dst)[1] = p1;
    }
    __syncthreads();

    for (int t = 0; t < TT; t++){
        const float* hr = (t & 1) ? g_hB : g_hA;
        float*       hw = (t & 1) ? g_hA : g_hB;

        unsigned long long acc[4][4];
        #pragma unroll
        for (int q = 0; q < 4; q++)
            #pragma unroll
            for (int i = 0; i < 4; i++) acc[q][i] = 0ull;

        for (int cn = 0; cn < NCH_E; cn++){
            // prefetch next chunk (chunk 0 of t+1 is x: no dependency on new h)
            float4 p0, p1; bool act;
            {
                int nc = cn + 1, nt = t;
                if (nc == NCH_E){ nc = 0; nt = t + 1; }
                act = (nt < TT);
                if (nc == 2 && t4 >= 2) act = false;
                if (act){
                    const float* src = (nc < 3)
                        ? traj + ((size_t)(row0+lr)*TT + nt)*DD + nc*32 + t4*8
                        : hr   + (size_t)(row0+lr)*HH + (nc-3)*32 + t4*8;
                    p0 = ((const float4*)src)[0];
                    p1 = ((const float4*)src)[1];
                }
            }
            // compute chunk cn from buffer pb
            {
                const float* hb = hs + pb*HS_BUF + (ty*4)*HS_STRIDE;
                int koff = (cn < 3) ? cn*32 : DD + (cn-3)*32;
                const float* wb = ws + tx*WSP_E + koff;
                if (cn == 2) mma_k<4, WSP_E>(acc, hb, wb);
                else         mma_k<8, WSP_E>(acc, hb, wb);
            }
            if (act){
                float* dst = &hs[(pb^1)*HS_BUF + lr*HS_STRIDE + t4*8];
                ((float4*)dst)[0] = p0; ((float4*)dst)[1] = p1;
            }
            pb ^= 1;
            if (cn < NCH_E-1) __syncthreads();
        }

        // elementwise LSTM update (c in registers)
        #pragma unroll
        for (int i = 0; i < 4; i++){
            float2 v0 = ull2f(acc[0][i]);
            float2 v1 = ull2f(acc[1][i]);
            float2 v2 = ull2f(acc[2][i]);
            float2 v3 = ull2f(acc[3][i]);
            float gi = v0.x + v0.y + bias[0];
            float gf = v1.x + v1.y + bias[1];
            float gg = v2.x + v2.y + bias[2];
            float go = v3.x + v3.y + bias[3];
            float cn_ = sigf(gf)*cst[i] + sigf(gi)*tanh_f(gg);
            cst[i] = cn_;
            hw[(size_t)(row0 + ty*4 + i)*HH + j] = sigf(go)*tanh_f(cn_);
        }
        grid_sync((unsigned)t);
    }
    // T even -> final hidden state in g_hA
}

// ---------------- VQ ----------------
__global__ void k_vq(const float* __restrict__ emb){
    int b = blockIdx.x, tid = threadIdx.x;
    __shared__ float zs[HH];
    __shared__ float rs[256];
    __shared__ int   rk[256];
    zs[tid]       = g_hA[(size_t)b*HH + tid];
    zs[tid + 256] = g_hA[(size_t)b*HH + tid + 256];
    __syncthreads();
    float bestS = 3.4e38f; int bestK = 0;
    #pragma unroll
    for (int kq = 0; kq < 2; kq++){
        int k = tid + kq*256;
        const float* e = emb + (size_t)k*HH;
        float s = 0.f, dt = 0.f;
        for (int jj = 0; jj < HH; jj++){ float ev = e[jj]; s += ev*ev; dt += ev*zs[jj]; }
        float score = s - 2.f*dt;
        if (score < bestS || (score == bestS && k < bestK)){ bestS = score; bestK = k; }
    }
    rs[tid] = bestS; rk[tid] = bestK;
    __syncthreads();
    for (int s = 128; s > 0; s >>= 1){
        if (tid < s){
            if (rs[tid+s] < rs[tid] || (rs[tid+s] == rs[tid] && rk[tid+s] < rk[tid])){
                rs[tid] = rs[tid+s]; rk[tid] = rk[tid+s];
            }
        }
        __syncthreads();
    }
    int idx = rk[0];
    if (tid == 0) g_idx[b] = idx;
    float lp = 0.f;
    #pragma unroll
    for (int kq = 0; kq < 2; kq++){
        int jj = tid + kq*256;
        float q = emb[(size_t)idx*HH + jj];
        g_quant[(size_t)b*HH + jj] = q;
        float dz = q - zs[jj];
        lp += dz*dz;
    }
    __syncthreads();
    rs[tid] = lp;
    __syncthreads();
    for (int s = 128; s > 0; s >>= 1){
        if (tid < s) rs[tid] += rs[tid+s];
        __syncthreads();
    }
    if (tid == 0) g_lossp[b] = rs[0];
}

__global__ void k_vqfinish(float* __restrict__ out){
    const size_t OFF = (size_t)BB*TT*DD;
    int tid = threadIdx.x;
    if (tid == 0){
        float tot = 0.f;
        for (int i = 0; i < BB; i++) tot += g_lossp[i];
        out[OFF] = 1.25f * tot / (float)(BB*HH);
    }
    out[OFF + 1 + tid] = (float)g_idx[tid];
}

// ---------------- persistent decoder ----------------
__global__ void __launch_bounds__(256, 1) k_decoder(){
    extern __shared__ float sm[];
    float* ws = sm;
    float* hs = sm + 64*WSP_D;
    const int tid = threadIdx.x;
    const int rg = blockIdx.x >> 5, cg = blockIdx.x & 31;
    const int row0 = rg*64, j0 = cg*16;
    const int tx = tid & 15, ty = tid >> 4;
    const int j = j0 + tx;
    const int lr = tid >> 2, t4 = tid & 3;

    {
        int c = tid >> 2, l4 = tid & 3;
        int n = (c >> 4)*512 + j0 + (c & 15);
        for (int k0 = l4*4; k0 < HH; k0 += 16)
            *(float4*)&ws[c*WSP_D + k0] = *(const float4*)&g_Wcomb[(size_t)n*HH + k0];
    }
    float bias[4];
    #pragma unroll
    for (int q = 0; q < 4; q++) bias[q] = g_bcomb[q*HH + j];
    float cst[4] = {0.f, 0.f, 0.f, 0.f};

    for (int t = 0; t < TT; t++){
        const float* hr = (t & 1) ? g_hB : g_hA;
        float*       hw = (t & 1) ? g_hA : g_hB;

        // stage chunk 0 (depends on h written last step -> after grid barrier)
        {
            const float* src = hr + (size_t)(row0+lr)*HH + t4*8;
            float4 p0 = ((const float4*)src)[0];
            float4 p1 = ((const float4*)src)[1];
            float* dst = &hs[0*HS_BUF + lr*HS_STRIDE + t4*8];
            ((float4*)dst)[0] = p0; ((float4*)dst)[1] = p1;
        }
        __syncthreads();

        unsigned long long acc[4][4];
        #pragma unroll
        for (int q = 0; q < 4; q++)
            #pragma unroll
            for (int i = 0; i < 4; i++) acc[q][i] = 0ull;

        for (int cn = 0; cn < NCH_D; cn++){
            float4 p0, p1; bool act = (cn + 1 < NCH_D);
            if (act){
                const float* src = hr + (size_t)(row0+lr)*HH + (cn+1)*32 + t4*8;
                p0 = ((const float4*)src)[0];
                p1 = ((const float4*)src)[1];
            }
            {
                const float* hb = hs + (cn & 1)*HS_BUF + (ty*4)*HS_STRIDE;
                const float* wb = ws + tx*WSP_D + cn*32;
                mma_k<8, WSP_D>(acc, hb, wb);
            }
            if (act){
                float* dst = &hs[((cn+1) & 1)*HS_BUF + lr*HS_STRIDE + t4*8];
                ((float4*)dst)[0] = p0; ((float4*)dst)[1] = p1;
            }
            if (cn < NCH_D-1) __syncthreads();
        }

        #pragma unroll
        for (int i = 0; i < 4; i++){
            int r = row0 + ty*4 + i;
            float2 v0 = ull2f(acc[0][i]);
            float2 v1 = ull2f(acc[1][i]);
            float2 v2 = ull2f(acc[2][i]);
            float2 v3 = ull2f(acc[3][i]);
            float gi = v0.x + v0.y + bias[0];
            float gf = v1.x + v1.y + bias[1];
            float gg = v2.x + v2.y + bias[2];
            float go = v3.x + v3.y + bias[3];
            if (t == 0){
                gi -= g_corr[(size_t)r*GG + 0*HH + j];
                gf -= g_corr[(size_t)r*GG + 1*HH + j];
                gg -= g_corr[(size_t)r*GG + 2*HH + j];
                go -= g_corr[(size_t)r*GG + 3*HH + j];
            }
            float cn_ = sigf(gf)*cst[i] + sigf(gi)*tanh_f(gg);
            cst[i] = cn_;
            float hv = sigf(go)*tanh_f(cn_);
            hw[(size_t)r*HH + j] = hv;
            g_Hbuf[((size_t)t*BB + r)*HH + j] = hv;
        }
        grid_sync((unsigned)t);
    }
}

// ---------------- recon head ----------------
__device__ __forceinline__ void stage_h32(float hsb[32][68], const float* __restrict__ src, int stride){
    int kk = threadIdx.x & 31, rb = threadIdx.x >> 5;
    #pragma unroll
    for (int i = 0; i < 8; i++)
        hsb[kk][rb + i*8] = src[(size_t)(rb + i*8)*stride + kk];
}

__global__ void __launch_bounds__(256) k_recon(const float* __restrict__ fcW,
                                               const float* __restrict__ fcb,
                                               float* __restrict__ out){
    __shared__ __align__(16) float hsb[32][68];
    __shared__ unsigned long long wsd[32][DD];
    int t = blockIdx.x;
    int b0 = blockIdx.y * 64;
    int tid = threadIdx.x;
    int txd = tid & 15, tyb = tid >> 4;

    unsigned long long acc[5][2];
    #pragma unroll
    for (int s = 0; s < 5; s++){ acc[s][0] = 0ull; acc[s][1] = 0ull; }

    for (int c = 0; c < 16; c++){
        __syncthreads();
        stage_h32(hsb, g_Hbuf + ((size_t)t*BB + b0)*HH + c*32, HH);
        {
            int kk = tid & 31, db = tid >> 5;
            #pragma unroll
            for (int i = 0; i < 10; i++){
                int d = db + i*8;
                wsd[kk][d] = dupf(fcW[(size_t)d*HH + c*32 + kk]);
            }
        }
        __syncthreads();
        #pragma unroll
        for (int kk = 0; kk < 32; kk++){
            ulonglong2 hp = *(const ulonglong2*)&hsb[kk][tyb*4];
            #pragma unroll
            for (int s = 0; s < 5; s++){
                unsigned long long w = wsd[kk][txd + 16*s];
                ffma2(acc[s][0], hp.x, w);
                ffma2(acc[s][1], hp.y, w);
            }
        }
    }
    #pragma unroll
    for (int s = 0; s < 5; s++){
        int d = txd + 16*s;
        float bv = fcb[d];
        #pragma unroll
        for (int p = 0; p < 2; p++){
            float2 v = ull2f(acc[s][p]);
            int b = b0 + tyb*4 + p*2;
            out[((size_t)b*TT + t)*DD + d]     = v.x + bv;
            out[((size_t)(b+1)*TT + t)*DD + d] = v.y + bv;
        }
    }
}

// ---------------- launcher ----------------
extern "C" void kernel_launch(void* const* d_in, const int* in_sizes, int n_in,
                              void* d_out, int out_size){
    (void)in_sizes; (void)n_in; (void)out_size;
    const float* traj = (const float*)d_in[0];
    const float* eWih = (const float*)d_in[2];
    const float* eWhh = (const float*)d_in[3];
    const float* ebi  = (const float*)d_in[4];
    const float* ebh  = (const float*)d_in[5];
    const float* emb  = (const float*)d_in[6];
    const float* dWih = (const float*)d_in[7];
    const float* dWhh = (const float*)d_in[8];
    const float* dbi  = (const float*)d_in[9];
    const float* dbh  = (const float*)d_in[10];
    const float* fcW  = (const float*)d_in[11];
    const float* fcb  = (const float*)d_in[12];
    float* out = (float*)d_out;

    const int SMEM_E = (64*WSP_E + 2*HS_BUF)*4;   // 171008 B
    const int SMEM_D = (64*WSP_D + 2*HS_BUF)*4;   // 150528 B
    cudaFuncSetAttribute(k_encoder, cudaFuncAttributeMaxDynamicSharedMemorySize, SMEM_E);
    cudaFuncSetAttribute(k_decoder, cudaFuncAttributeMaxDynamicSharedMemorySize, SMEM_D);

    k_bias<<<8, 256>>>(ebi, ebh, dbi, dbh, dWih, fcb);
    k_wcomb<<<512, 256>>>(dWih, dWhh, fcW);
    k_init<<<512, 256>>>();
    k_encoder<<<NBLK, 256, SMEM_E>>>(traj, eWih, eWhh);
    k_vq<<<BB, 256>>>(emb);
    k_vqfinish<<<1, 256>>>(out);
    k_x1<<<BB, 256>>>(fcW, fcb);
    k_corr<<<GG, 256>>>(dWih);
    k_decinit<<<512, 256>>>();
    k_decoder<<<NBLK, 256, SMEM_D>>>();
    k_recon<<<dim3(TT, 4), 256>>>(fcW, fcb, out);
}